// round 1
// baseline (speedup 1.0000x reference)
#include <cuda_runtime.h>
#include <math.h>

// ---------------- constants ----------------
#define NB      64        // combined batch: 0..31 = x, 32..63 = -x
#define NPATCH  16
#define PATCH   32
#define DMODEL  1024
#define NH      16
#define HDIM    64
#define NDFF    4096
#define NLAYER  8
#define CMAX    20        // max kv cache length (16 prefill + 4 AR)
#define T1      1024      // prefill tokens = 64 * 16
#define T2      256       // AR tokens = 64 * 4
#define EPSF    1e-6f

// ---------------- device scratch (static, no allocation) ----------------
__device__ float g_normed[T1 * PATCH];
__device__ float g_anorm [T2 * PATCH];
__device__ float g_ctxmu [NB * NPATCH];
__device__ float g_ctxsg [NB * NPATCH];
__device__ float g_nmu   [NB * 4];
__device__ float g_nsg   [NB * 4];
__device__ int   g_ispos [32];
__device__ float g_hdd [T1 * DMODEL];
__device__ float g_xn  [T1 * DMODEL];
__device__ float g_qkv [T1 * 3 * DMODEL];
__device__ float g_attb[T1 * DMODEL];
__device__ float g_h1  [T1 * NDFF];
__device__ float g_Kc  [NLAYER * NB * CMAX * DMODEL];
__device__ float g_Vc  [NLAYER * NB * CMAX * DMODEL];
__device__ float g_no1 [NB * 128];
__device__ float g_no2 [NB * 128];
__device__ float g_last[NB * 128];

// ---------------- helpers ----------------
__device__ __forceinline__ float warpSum(float v) {
#pragma unroll
    for (int o = 16; o; o >>= 1) v += __shfl_xor_sync(0xffffffffu, v, o);
    return v;
}

__device__ __forceinline__ float gelu_tanh(float x) {
    // jax.nn.gelu default (approximate=True)
    float x3 = x * x * x;
    return 0.5f * x * (1.0f + tanhf(0.7978845608028654f * (x + 0.044715f * x3)));
}

// ---------------- running stats (Welford batch update, exact formula) ------
// grid 64 blocks (one per combined-batch row), 32 threads (one warp)
__global__ void stats_kernel(const float* __restrict__ x) {
    int b = blockIdx.x, lane = threadIdx.x;
    const float* xb = x + (size_t)(b & 31) * 512;
    float sign = (b < 32) ? 1.f : -1.f;
    if (b < 32) {
        bool ok = true;
        for (int i = lane; i < 512; i += 32) ok = ok && (xb[i] >= 0.f);
        unsigned bal = __ballot_sync(0xffffffffu, ok);
        if (lane == 0) g_ispos[b] = (bal == 0xffffffffu) ? 1 : 0;
    }
    float n = 0.f, mu = 0.f, sg = 0.f;
    for (int p = 0; p < NPATCH; p++) {
        float v = sign * xb[p * PATCH + lane];
        float s = warpSum(v);
        float nn = n + 32.f;
        float nmu = (n * mu + s) / nn;
        float m2 = n * sg * sg + warpSum((v - mu) * (v - nmu));
        float nsg = sqrtf(fmaxf(m2 / nn, 1e-12f));
        n = nn; mu = nmu; sg = nsg;
        if (lane == 0) { g_ctxmu[b * NPATCH + p] = mu; g_ctxsg[b * NPATCH + p] = sg; }
        g_normed[(b * NPATCH + p) * PATCH + lane] = (v - mu) / (sg + EPSF);
    }
}

// AR-step stats: continue the Welford carry (n=512) with 4 patches from g_last
__global__ void ar_stats_kernel() {
    int b = blockIdx.x, lane = threadIdx.x;
    float n = 512.f, mu = g_ctxmu[b * NPATCH + 15], sg = g_ctxsg[b * NPATCH + 15];
    for (int p = 0; p < 4; p++) {
        float v = g_last[b * 128 + p * PATCH + lane];
        float s = warpSum(v);
        float nn = n + 32.f;
        float nmu = (n * mu + s) / nn;
        float m2 = n * sg * sg + warpSum((v - mu) * (v - nmu));
        float ns = sqrtf(fmaxf(m2 / nn, 1e-12f));
        n = nn; mu = nmu; sg = ns;
        if (lane == 0) { g_nmu[b * 4 + p] = mu; g_nsg[b * 4 + p] = sg; }
        g_anorm[(b * 4 + p) * PATCH + lane] = (v - mu) / (sg + EPSF);
    }
}

// ---------------- layernorm: one block per token row ----------------
__global__ void ln_kernel(const float* __restrict__ in, const float* __restrict__ sc,
                          float* __restrict__ out) {
    __shared__ float row[DMODEL];
    __shared__ float red[8];
    __shared__ float s_mean, s_inv;
    int r = blockIdx.x, tid = threadIdx.x;
    const float* xr = in + (size_t)r * DMODEL;
    float ls = 0.f;
    for (int c = tid; c < DMODEL; c += 256) { float v = xr[c]; row[c] = v; ls += v; }
    ls = warpSum(ls);
    if ((tid & 31) == 0) red[tid >> 5] = ls;
    __syncthreads();
    if (tid < 8) {
        float t = red[tid];
#pragma unroll
        for (int o = 4; o; o >>= 1) t += __shfl_xor_sync(0xffu, t, o);
        if (tid == 0) s_mean = t / (float)DMODEL;
    }
    __syncthreads();
    float m = s_mean;
    float lv = 0.f;
    for (int c = tid; c < DMODEL; c += 256) { float d = row[c] - m; lv += d * d; }
    lv = warpSum(lv);
    if ((tid & 31) == 0) red[tid >> 5] = lv;
    __syncthreads();
    if (tid < 8) {
        float t = red[tid];
#pragma unroll
        for (int o = 4; o; o >>= 1) t += __shfl_xor_sync(0xffu, t, o);
        if (tid == 0) s_inv = rsqrtf(t / (float)DMODEL + EPSF);
    }
    __syncthreads();
    float inv = s_inv;
    for (int c = tid; c < DMODEL; c += 256)
        out[(size_t)r * DMODEL + c] = (row[c] - m) * inv * sc[c];
}

// ---------------- generic tiled fp32 GEMM ----------------
// C[M,N] = op( A[rowmap, K] * B[colmap] )  row-major
//  A row r maps to physical row (aRowStart + r*aRowStep)
//  B col c maps to physical col (bColStart + c*bColStep)
//  flags: 1 = C += result (residual), 2 = gelu, 4 = add bias[c]
#define BM 64
#define BN 64
#define BKK 16
__global__ void gemm_kernel(const float* __restrict__ A, const float* __restrict__ B,
                            const float* __restrict__ bias, float* __restrict__ C,
                            int M, int N, int K,
                            int lda, int aRowStart, int aRowStep,
                            int ldb, int bColStart, int bColStep,
                            int ldc, int flags) {
    __shared__ float As[BKK][BM + 4];
    __shared__ float Bs[BKK][BN + 4];
    int tid = threadIdx.y * 16 + threadIdx.x;
    int rowBase = blockIdx.y * BM;
    int colBase = blockIdx.x * BN;
    int r0 = threadIdx.y * 4, c0 = threadIdx.x * 4;
    float acc[4][4] = {};
    int aRow = tid >> 2;          // 0..63
    int aK   = (tid & 3) * 4;     // 0,4,8,12
    int bRow = tid >> 4;          // 0..15
    int bCol = (tid & 15) * 4;    // 0..60

    for (int kk = 0; kk < K; kk += BKK) {
        {
            int gr = rowBase + aRow;
            float4 v = make_float4(0.f, 0.f, 0.f, 0.f);
            if (gr < M) {
                const float* src = A + (size_t)(aRowStart + gr * aRowStep) * lda + kk + aK;
                v = *(const float4*)src;
            }
            As[aK + 0][aRow] = v.x; As[aK + 1][aRow] = v.y;
            As[aK + 2][aRow] = v.z; As[aK + 3][aRow] = v.w;
        }
        {
            int gc = colBase + bCol;
            if (bColStep == 1) {
                float4 v = make_float4(0.f, 0.f, 0.f, 0.f);
                if (gc < N) {
                    const float* src = B + (size_t)(kk + bRow) * ldb + bColStart + gc;
                    v = *(const float4*)src;
                }
                Bs[bRow][bCol + 0] = v.x; Bs[bRow][bCol + 1] = v.y;
                Bs[bRow][bCol + 2] = v.z; Bs[bRow][bCol + 3] = v.w;
            } else {
#pragma unroll
                for (int j = 0; j < 4; j++) {
                    int c = gc + j;
                    Bs[bRow][bCol + j] = (c < N)
                        ? B[(size_t)(kk + bRow) * ldb + bColStart + c * bColStep] : 0.f;
                }
            }
        }
        __syncthreads();
#pragma unroll
        for (int k = 0; k < BKK; k++) {
            float a[4], bb[4];
#pragma unroll
            for (int i = 0; i < 4; i++) a[i] = As[k][r0 + i];
#pragma unroll
            for (int j = 0; j < 4; j++) bb[j] = Bs[k][c0 + j];
#pragma unroll
            for (int i = 0; i < 4; i++)
#pragma unroll
                for (int j = 0; j < 4; j++) acc[i][j] += a[i] * bb[j];
        }
        __syncthreads();
    }
#pragma unroll
    for (int i = 0; i < 4; i++) {
        int r = rowBase + r0 + i;
        if (r >= M) continue;
#pragma unroll
        for (int j = 0; j < 4; j++) {
            int c = colBase + c0 + j;
            if (c >= N) continue;
            float v = acc[i][j];
            if (flags & 4) v += bias[c];
            if (flags & 2) v = gelu_tanh(v);
            size_t o = (size_t)r * ldc + c;
            if (flags & 1) C[o] += v; else C[o] = v;
        }
    }
}

static void launch_gemm(const float* A, const float* B, const float* bias, float* C,
                        int M, int N, int K,
                        int lda, int ars, int arstep,
                        int ldb, int bcs, int bcstep,
                        int ldc, int flags) {
    dim3 grid((N + BN - 1) / BN, (M + BM - 1) / BM), block(16, 16);
    gemm_kernel<<<grid, block>>>(A, B, bias, C, M, N, K, lda, ars, arstep,
                                 ldb, bcs, bcstep, ldc, flags);
}

// ---------------- KV cache append ----------------
__global__ void copy_kv_kernel(const float* __restrict__ qkv, float* __restrict__ Kc,
                               float* __restrict__ Vc, int N, int off) {
    int t = blockIdx.x; int b = t / N, n = t % N;
    size_t dst = ((size_t)b * CMAX + off + n) * DMODEL;
    size_t src = (size_t)t * 3 * DMODEL;
    for (int c = threadIdx.x; c < DMODEL; c += blockDim.x) {
        Kc[dst + c] = qkv[src + DMODEL + c];
        Vc[dst + c] = qkv[src + 2 * DMODEL + c];
    }
}

// ---------------- attention: one warp per (b,h,query) ----------------
__global__ void attn_kernel(const float* __restrict__ qkv, const float* __restrict__ Kc,
                            const float* __restrict__ Vc, float* __restrict__ out,
                            int N, int C, int off) {
    int bh = blockIdx.x; int b = bh / NH, h = bh % NH;
    int n = threadIdx.y, lane = threadIdx.x;
    int t = b * N + n;
    const float* q = qkv + (size_t)t * 3 * DMODEL + h * HDIM;
    int lim = n + off;                 // keys m <= lim allowed (causal)
    float s = -1e30f;
    if (lane < C && lane <= lim) {
        const float* kr = Kc + ((size_t)b * CMAX + lane) * DMODEL + h * HDIM;
        float d = 0.f;
#pragma unroll
        for (int i = 0; i < HDIM; i++) d += q[i] * kr[i];
        s = d * 0.125f;                // HD^-0.5
    }
    float mx = s;
#pragma unroll
    for (int o = 16; o; o >>= 1) mx = fmaxf(mx, __shfl_xor_sync(0xffffffffu, mx, o));
    float p = (lane < C && lane <= lim) ? expf(s - mx) : 0.f;
    float sum = warpSum(p);
    float a0 = 0.f, a1 = 0.f;
    int mmax = min(lim, C - 1);
    for (int m = 0; m <= mmax; m++) {
        float pm = __shfl_sync(0xffffffffu, p, m);
        const float* vr = Vc + ((size_t)b * CMAX + m) * DMODEL + h * HDIM;
        a0 += pm * vr[lane];
        a1 += pm * vr[lane + 32];
    }
    float inv = 1.f / sum;
    out[(size_t)t * DMODEL + h * HDIM + lane]      = a0 * inv;
    out[(size_t)t * DMODEL + h * HDIM + lane + 32] = a1 * inv;
}

// ---------------- epilogue kernels ----------------
__global__ void revin_last_kernel() {
    int b = blockIdx.x, o = threadIdx.x;
    g_last[b * 128 + o] = g_no1[b * 128 + o] * (g_ctxsg[b * NPATCH + 15] + EPSF)
                        + g_ctxmu[b * NPATCH + 15];
}

__global__ void assemble_kernel(float* __restrict__ out) {
    int idx = blockIdx.x * blockDim.x + threadIdx.x;
    int b = idx / 256, t = idx % 256;
    float m;
    if (t < 128) {
        m = 0.5f * (g_last[b * 128 + t] - g_last[(b + 32) * 128 + t]);
    } else {
        int o = t - 128;
        float va = g_no2[b * 128 + o]        * (g_nsg[b * 4 + 3] + EPSF)        + g_nmu[b * 4 + 3];
        float vb = g_no2[(b + 32) * 128 + o] * (g_nsg[(b + 32) * 4 + 3] + EPSF) + g_nmu[(b + 32) * 4 + 3];
        m = 0.5f * (va - vb);
    }
    if (g_ispos[b]) m = fmaxf(m, 0.f);
    out[idx] = m;
}

// ---------------- full transformer forward ----------------
static void model_fwd_host(int T, int N, int C, int off,
                           const float* in_tok,
                           const float* W_in, const float* b_in, const float* ln1,
                           const float* Wqkv, const float* Wo, const float* ln2,
                           const float* W1, const float* W2, const float* lnf,
                           const float* Wout,
                           float* hdd, float* xn, float* qkv, float* att, float* h1,
                           float* Kc, float* Vc,
                           float* nosel, int selStart, int selStep) {
    // embed: feat @ W_in (mask half is zero -> first 32 rows only) + b_in
    launch_gemm(in_tok, W_in, b_in, hdd, T, DMODEL, PATCH,
                PATCH, 0, 1, DMODEL, 0, 1, DMODEL, 4);
    for (int l = 0; l < NLAYER; l++) {
        ln_kernel<<<T, 256>>>(hdd, ln1 + (size_t)l * DMODEL, xn);
        launch_gemm(xn, Wqkv + (size_t)l * DMODEL * 3 * DMODEL, nullptr, qkv,
                    T, 3 * DMODEL, DMODEL, DMODEL, 0, 1, 3 * DMODEL, 0, 1, 3 * DMODEL, 0);
        float* Kl = Kc + (size_t)l * NB * CMAX * DMODEL;
        float* Vl = Vc + (size_t)l * NB * CMAX * DMODEL;
        copy_kv_kernel<<<T, 256>>>(qkv, Kl, Vl, N, off);
        attn_kernel<<<NB * NH, dim3(32, N)>>>(qkv, Kl, Vl, att, N, C, off);
        launch_gemm(att, Wo + (size_t)l * DMODEL * DMODEL, nullptr, hdd,
                    T, DMODEL, DMODEL, DMODEL, 0, 1, DMODEL, 0, 1, DMODEL, 1);
        ln_kernel<<<T, 256>>>(hdd, ln2 + (size_t)l * DMODEL, xn);
        launch_gemm(xn, W1 + (size_t)l * DMODEL * NDFF, nullptr, h1,
                    T, NDFF, DMODEL, DMODEL, 0, 1, NDFF, 0, 1, NDFF, 2);
        launch_gemm(h1, W2 + (size_t)l * NDFF * DMODEL, nullptr, hdd,
                    T, DMODEL, NDFF, NDFF, 0, 1, DMODEL, 0, 1, DMODEL, 1);
    }
    ln_kernel<<<T, 256>>>(hdd, lnf, xn);
    // Wout, channel-5 columns only (cols o*10+5), last token of each batch row
    launch_gemm(xn, Wout, nullptr, nosel, NB, 128, DMODEL,
                DMODEL, selStart, selStep, 1280, 5, 10, 128, 0);
}

// ---------------- entry ----------------
extern "C" void kernel_launch(void* const* d_in, const int* in_sizes, int n_in,
                              void* d_out, int out_size) {
    const float* x     = (const float*)d_in[0];
    const float* W_in  = (const float*)d_in[1];
    const float* b_in  = (const float*)d_in[2];
    const float* ln1_s = (const float*)d_in[3];
    const float* Wqkv  = (const float*)d_in[4];
    const float* Wo    = (const float*)d_in[5];
    const float* ln2_s = (const float*)d_in[6];
    const float* W1    = (const float*)d_in[7];
    const float* W2    = (const float*)d_in[8];
    const float* lnf_s = (const float*)d_in[9];
    const float* Wout  = (const float*)d_in[10];
    // d_in[11] = Wqs: provably unused for the median output (channel 5)

    float *normed, *anorm, *hdd, *xn, *qkv, *att, *h1, *Kc, *Vc, *no1, *no2;
    cudaGetSymbolAddress((void**)&normed, g_normed);
    cudaGetSymbolAddress((void**)&anorm,  g_anorm);
    cudaGetSymbolAddress((void**)&hdd,    g_hdd);
    cudaGetSymbolAddress((void**)&xn,     g_xn);
    cudaGetSymbolAddress((void**)&qkv,    g_qkv);
    cudaGetSymbolAddress((void**)&att,    g_attb);
    cudaGetSymbolAddress((void**)&h1,     g_h1);
    cudaGetSymbolAddress((void**)&Kc,     g_Kc);
    cudaGetSymbolAddress((void**)&Vc,     g_Vc);
    cudaGetSymbolAddress((void**)&no1,    g_no1);
    cudaGetSymbolAddress((void**)&no2,    g_no2);

    // Stage A: running stats + normalization for x and -x (batch 64)
    stats_kernel<<<NB, 32>>>(x);

    // Stage B: prefill, 16 patches/batch, cache offset 0, C=16
    model_fwd_host(T1, NPATCH, 16, 0, normed,
                   W_in, b_in, ln1_s, Wqkv, Wo, ln2_s, W1, W2, lnf_s, Wout,
                   hdd, xn, qkv, att, h1, Kc, Vc,
                   no1, /*selStart=*/15, /*selStep=*/16);
    revin_last_kernel<<<NB, 128>>>();

    // Stage C: AR stats + 1 autoregressive step (4 patches, cache 16..19, C=20)
    ar_stats_kernel<<<NB, 32>>>();
    model_fwd_host(T2, 4, 20, 16, anorm,
                   W_in, b_in, ln1_s, Wqkv, Wo, ln2_s, W1, W2, lnf_s, Wout,
                   hdd, xn, qkv, att, h1, Kc, Vc,
                   no2, /*selStart=*/3, /*selStep=*/4);

    // Stage D: combine x / -x passes, clamp, write [32,256]
    assemble_kernel<<<32, 256>>>((float*)d_out);
}